// round 11
// baseline (speedup 1.0000x reference)
#include <cuda_runtime.h>
#include <cuda_fp16.h>
#include <math.h>
#include <stdint.h>

// ===========================================================================
// Fused INR via warp-level mma.sync, fp16 2-product split, fp32 accum.
// R10: ping-pong activation planes -> 1 barrier/layer (was 2), straight-line
//      sin->pack->STS epilogue. Weights fp16 hi+lo (exact), acts fp16.
// ===========================================================================

#define OMEGA0    30.0f
#define TWO_PI_F  6.283185307179586f
#define THREADS   512

#define NTILES    (512 + 5 * 1024)      // 5632 (mt,ks) tiles total
#define PLANE_U32 (NTILES * 128)        // u32 per plane (tile=128 u32)

__device__ __align__(16) uint32_t g_wfrag[2 * PLANE_U32];   // hi plane, lo plane

// ---- SMEM layout (bytes) ----
#define SM_WOUT  0                       // 1536 floats
#define SM_CS    6144                    // 192 floats
#define SM_BFF   6912                    // 384 floats
#define SM_P0    9216                    // act plane 0: 512 rows x 128B
#define SM_P1    (SM_P0 + 65536)         // act plane 1
#define SMEM_BYTES (SM_P1 + 65536)       // 140288

// ---------------- helpers ----------------
__device__ __forceinline__ uint32_t smem_u32(const void* p) {
    uint32_t a;
    asm("{ .reg .u64 t; cvta.to.shared.u64 t, %1; cvt.u32.u64 %0, t; }"
        : "=r"(a) : "l"(p));
    return a;
}
__device__ __forceinline__ void mma16816(float* d, const uint4& a,
                                         uint32_t b0, uint32_t b1) {
    asm volatile(
        "mma.sync.aligned.m16n8k16.row.col.f32.f16.f16.f32 "
        "{%0,%1,%2,%3}, {%4,%5,%6,%7}, {%8,%9}, {%0,%1,%2,%3};"
        : "+f"(d[0]), "+f"(d[1]), "+f"(d[2]), "+f"(d[3])
        : "r"(a.x), "r"(a.y), "r"(a.z), "r"(a.w), "r"(b0), "r"(b1));
}
__device__ __forceinline__ void ldmx4t(uint32_t& r0, uint32_t& r1,
                                       uint32_t& r2, uint32_t& r3,
                                       uint32_t addr) {
    asm volatile(
        "ldmatrix.sync.aligned.m8n8.x4.trans.shared.b16 {%0,%1,%2,%3}, [%4];"
        : "=r"(r0), "=r"(r1), "=r"(r2), "=r"(r3) : "r"(addr));
}
__device__ __forceinline__ uint16_t hfb(float v) {
    __half h = __float2half_rn(v);
    return *reinterpret_cast<uint16_t*>(&h);
}
__device__ __forceinline__ float hff(uint16_t b) {
    __half h = *reinterpret_cast<__half*>(&b);
    return __half2float(h);
}

// store v (fp16) to (row, col n) in a plane, swizzled
__device__ __forceinline__ void store1(unsigned char* plane, int row, int n, float v) {
    uint32_t off = (uint32_t)row * 128u + (((uint32_t)n * 2u) ^ (((uint32_t)row & 7u) << 4));
    *(uint16_t*)(plane + off) = hfb(v);
}

// ---------------- weight prep: fp32 -> fragment-ordered fp16 hi/lo ----------
__global__ void prep_weights(const float* __restrict__ Wf,
                             const float* __restrict__ Wh) {
    int idx = blockIdx.x * blockDim.x + threadIdx.x;
    if (idx >= 2 * PLANE_U32) return;
    int p   = idx / PLANE_U32;
    int rem = idx - p * PLANE_U32;
    int tile = rem >> 7;
    int li   = rem & 127;
    int lane = li >> 2, q = li & 3;

    const float* src; int K, mt, ks;
    if (tile < 512) { mt = tile >> 4; ks = tile & 15; K = 256; src = Wf; }
    else {
        int th = tile - 512;
        int l = th >> 10, tt = th & 1023;
        mt = tt >> 5; ks = tt & 31; K = 512;
        src = Wh + (size_t)l * 512 * 512;
    }
    int r  = lane >> 2, c2 = (lane & 3) * 2;
    int row = mt * 16 + r + (q & 1) * 8;
    int k   = ks * 16 + c2 + (q >> 1) * 8;
    float w0 = src[(size_t)row * K + k];
    float w1 = src[(size_t)row * K + k + 1];
    uint16_t h0 = hfb(w0), h1 = hfb(w1);
    uint16_t o0, o1;
    if (p == 0) { o0 = h0; o1 = h1; }
    else        { o0 = hfb(w0 - hff(h0)); o1 = hfb(w1 - hff(h1)); }
    g_wfrag[idx] = ((uint32_t)o1 << 16) | (uint32_t)o0;
}

// ---------------- one sine layer: src plane -> dst plane ----------------
template <int KS>
__device__ __forceinline__ void run_layer(
    unsigned char* dst, uint32_t src_u32,
    const uint32_t* __restrict__ whi,
    const uint32_t* __restrict__ wlo,
    const float* __restrict__ bias,
    int wid, int lane)
{
    float acc[2][8][4];
#pragma unroll
    for (int a = 0; a < 2; ++a)
#pragma unroll
        for (int b = 0; b < 8; ++b)
#pragma unroll
            for (int c = 0; c < 4; ++c) acc[a][b][c] = 0.0f;

    const int r  = lane >> 2;
    const int cq = lane & 3;
    const int mid  = lane >> 3;
    const int rrow = lane & 7;
    const uint32_t rswz = (uint32_t)rrow << 4;
    const uint32_t krow_off = ((uint32_t)((mid & 1) * 8 + rrow)) * 128u;
    const uint32_t nb_base  = (uint32_t)((mid >> 1) * 8) * 2u;

    const uint32_t* pA0h = whi + (size_t)((wid * 2 + 0) * KS) * 128 + lane * 4;
    const uint32_t* pA0l = wlo + (size_t)((wid * 2 + 0) * KS) * 128 + lane * 4;
    const uint32_t* pA1h = whi + (size_t)((wid * 2 + 1) * KS) * 128 + lane * 4;
    const uint32_t* pA1l = wlo + (size_t)((wid * 2 + 1) * KS) * 128 + lane * 4;

    // prefetch A for ks=0
    uint4 Ah0 = *(const uint4*)pA0h;
    uint4 Al0 = *(const uint4*)pA0l;
    uint4 Ah1 = *(const uint4*)pA1h;
    uint4 Al1 = *(const uint4*)pA1l;

#pragma unroll 1
    for (int ks = 0; ks < KS; ++ks) {
        // prefetch next A (issued before any consumer of current A)
        uint4 nAh0, nAl0, nAh1, nAl1;
        if (ks + 1 < KS) {
            nAh0 = *(const uint4*)(pA0h + (ks + 1) * 128);
            nAl0 = *(const uint4*)(pA0l + (ks + 1) * 128);
            nAh1 = *(const uint4*)(pA1h + (ks + 1) * 128);
            nAl1 = *(const uint4*)(pA1l + (ks + 1) * 128);
        }

        // ---- B fragments: 4x ldmatrix.x4.trans = full n64 k16 ----
        uint32_t B[16];
        const uint32_t kbase = (uint32_t)ks * 16u * 128u + krow_off;
#pragma unroll
        for (int j = 0; j < 4; ++j) {
            uint32_t nb = ((uint32_t)j * 32u + nb_base) ^ rswz;
            ldmx4t(B[4 * j], B[4 * j + 1], B[4 * j + 2], B[4 * j + 3],
                   src_u32 + kbase + nb);
        }

        // ---- MMAs: 2 products x 2 m-tiles x 8 n-tiles = 32 ----
#pragma unroll
        for (int nt = 0; nt < 8; ++nt) {
            mma16816(acc[0][nt], Ah0, B[nt * 2], B[nt * 2 + 1]);
            mma16816(acc[1][nt], Ah1, B[nt * 2], B[nt * 2 + 1]);
        }
#pragma unroll
        for (int nt = 0; nt < 8; ++nt) {
            mma16816(acc[0][nt], Al0, B[nt * 2], B[nt * 2 + 1]);
            mma16816(acc[1][nt], Al1, B[nt * 2], B[nt * 2 + 1]);
        }
        Ah0 = nAh0; Al0 = nAl0; Ah1 = nAh1; Al1 = nAl1;
    }

    // ---- epilogue: sin -> f16x2 pack -> STS to dst (no barrier needed) ----
#pragma unroll
    for (int mtl = 0; mtl < 2; ++mtl) {
        const int row0 = wid * 32 + mtl * 16 + r;
        const int row1 = row0 + 8;
        const float ob0 = OMEGA0 * __ldg(bias + row0);
        const float ob1 = OMEGA0 * __ldg(bias + row1);
        const uint32_t sw0 = ((uint32_t)row0 & 7u) << 4;
        const uint32_t sw1 = ((uint32_t)row1 & 7u) << 4;
#pragma unroll
        for (int nt = 0; nt < 8; ++nt) {
            const int n = nt * 8 + cq * 2;
            float v00 = __sinf(fmaf(OMEGA0, acc[mtl][nt][0], ob0));
            float v01 = __sinf(fmaf(OMEGA0, acc[mtl][nt][1], ob0));
            float v10 = __sinf(fmaf(OMEGA0, acc[mtl][nt][2], ob1));
            float v11 = __sinf(fmaf(OMEGA0, acc[mtl][nt][3], ob1));
            uint32_t hp0, hp1;
            asm("cvt.rn.f16x2.f32 %0, %1, %2;"
                : "=r"(hp0) : "f"(v01), "f"(v00));
            asm("cvt.rn.f16x2.f32 %0, %1, %2;"
                : "=r"(hp1) : "f"(v11), "f"(v10));
            uint32_t off0 = (uint32_t)row0 * 128u + (((uint32_t)n * 2u) ^ sw0);
            uint32_t off1 = (uint32_t)row1 * 128u + (((uint32_t)n * 2u) ^ sw1);
            *(uint32_t*)(dst + off0) = hp0;
            *(uint32_t*)(dst + off1) = hp1;
        }
    }
    __syncthreads();   // dst visible; src free for reuse as next dst
}

// ---------------- main kernel ----------------
__global__ void __launch_bounds__(THREADS, 1)
inr_mma_kernel(const float* __restrict__ coords,
               const float* __restrict__ B_ff,
               const float* __restrict__ b_first,
               const float* __restrict__ b_hidden,
               const float* __restrict__ W_out,
               const float* __restrict__ b_out,
               float* __restrict__ out, int L)
{
    extern __shared__ unsigned char sm[];
    float* wout = (float*)(sm + SM_WOUT);
    float* cs   = (float*)(sm + SM_CS);
    float* bff  = (float*)(sm + SM_BFF);
    unsigned char* p0 = sm + SM_P0;
    unsigned char* p1 = sm + SM_P1;
    const uint32_t p0u = smem_u32(p0);
    const uint32_t p1u = smem_u32(p1);

    const int tid  = threadIdx.x;
    const int wid  = tid >> 5;
    const int lane = tid & 31;
    const int pt0  = blockIdx.x * 64;

    if (tid < 192) {
        int g = pt0 * 3 + tid;
        cs[tid] = (g < L * 3) ? coords[g] : 0.0f;
    }
    for (int i = tid; i < 384; i += THREADS) bff[i] = B_ff[i];
    __syncthreads();

    // Fourier features -> plane 0. sin(2*pi*t) == sin(2*pi*(t - rint(t))).
    for (int e = tid; e < 8192; e += THREADS) {
        int j = e >> 6, m = e & 63;
        float t = cs[m * 3 + 0] * bff[j] +
                  cs[m * 3 + 1] * bff[128 + j] +
                  cs[m * 3 + 2] * bff[256 + j];
        float f = t - rintf(t);
        float ang = TWO_PI_F * f;
        store1(p0, j, m, __sinf(ang));
        store1(p0, 128 + j, m, __cosf(ang));
    }
    __syncthreads();

    // layer 0: K=256, P0 -> P1
    run_layer<16>(p1, p0u, g_wfrag, g_wfrag + PLANE_U32, b_first, wid, lane);
    // hidden layers: K=512, alternate planes (l even: P1->P0, odd: P0->P1)
#pragma unroll 1
    for (int l = 0; l < 5; ++l) {
        const size_t base = (size_t)(512 + l * 1024) * 128;
        unsigned char* dst = (l & 1) ? p1 : p0;
        uint32_t src = (l & 1) ? p0u : p1u;
        run_layer<32>(dst, src, g_wfrag + base,
                      g_wfrag + PLANE_U32 + base,
                      b_hidden + l * 512, wid, lane);
    }
    // after 5 hidden layers (l=0..4): final activations in P0

    // ---- output linear 512 -> 3: all 512 threads (8 k-slices per point) ----
    for (int f = tid; f < 1536; f += THREADS) wout[f] = W_out[f];
    __syncthreads();
    {
        const int p = tid >> 3;        // point 0..63
        const int s = tid & 7;         // k-slice 0..7
        float a0 = 0.0f, a1 = 0.0f, a2 = 0.0f;
#pragma unroll 4
        for (int kk = 0; kk < 64; ++kk) {
            const int k = s * 64 + kk;
            uint32_t off = (uint32_t)k * 128u +
                           (((uint32_t)p * 2u) ^ (((uint32_t)k & 7u) << 4));
            float hv = hff(*(uint16_t*)(p0 + off));
            a0 = fmaf(hv, wout[k], a0);
            a1 = fmaf(hv, wout[512 + k], a1);
            a2 = fmaf(hv, wout[1024 + k], a2);
        }
#pragma unroll
        for (int d = 4; d >= 1; d >>= 1) {
            a0 += __shfl_down_sync(0xFFFFFFFFu, a0, d);
            a1 += __shfl_down_sync(0xFFFFFFFFu, a1, d);
            a2 += __shfl_down_sync(0xFFFFFFFFu, a2, d);
        }
        if (s == 0) {
            int gp = pt0 + p;
            if (gp < L) {
                out[gp * 3 + 0] = a0 + __ldg(b_out + 0);
                out[gp * 3 + 1] = a1 + __ldg(b_out + 1);
                out[gp * 3 + 2] = a2 + __ldg(b_out + 2);
            }
        }
    }
}

// ---------------- launcher ----------------
extern "C" void kernel_launch(void* const* d_in, const int* in_sizes, int n_in,
                              void* d_out, int out_size) {
    const float* coords   = (const float*)d_in[0];
    const float* B_ff     = (const float*)d_in[1];
    const float* W_first  = (const float*)d_in[2];
    const float* b_first  = (const float*)d_in[3];
    const float* W_hidden = (const float*)d_in[4];
    const float* b_hidden = (const float*)d_in[5];
    const float* W_out    = (const float*)d_in[6];
    const float* b_out    = (const float*)d_in[7];
    float* out = (float*)d_out;

    int L = in_sizes[0] / 3;
    int tiles = (L + 63) / 64;

    const int prep_n = 2 * PLANE_U32;
    prep_weights<<<(prep_n + 255) / 256, 256>>>(W_first, W_hidden);

    cudaFuncSetAttribute(inr_mma_kernel,
                         cudaFuncAttributeMaxDynamicSharedMemorySize,
                         SMEM_BYTES);
    inr_mma_kernel<<<tiles, THREADS, SMEM_BYTES>>>(
        coords, B_ff, b_first, b_hidden, W_out, b_out, out, L);
}

// round 12
// speedup vs baseline: 1.6886x; 1.6886x over previous
#include <cuda_runtime.h>
#include <cuda_fp16.h>
#include <math.h>
#include <stdint.h>

// ===========================================================================
// Fused INR via warp-level mma.sync, fp16 single-product weights, fp32 accum.
// R11: weights = fp16 (one plane), acts = fp16 -> 16 MMAs/k-step (half of
//      R10). Freed registers fund B-fragment double buffering (k-unroll 2).
//      Predicted rel_err ~6e-4 (act-rounding 4.2e-4 (+) W-rounding ~4e-4).
// ===========================================================================

#define OMEGA0    30.0f
#define TWO_PI_F  6.283185307179586f
#define THREADS   512

#define NTILES    (512 + 5 * 1024)      // 5632 (mt,ks) tiles total
#define PLANE_U32 (NTILES * 128)        // u32 per plane (tile=128 u32)

__device__ __align__(16) uint32_t g_wfrag[PLANE_U32];   // fp16 weight fragments

// ---- SMEM layout (bytes) ----
#define SM_WOUT  0                       // 1536 floats
#define SM_CS    6144                    // 192 floats
#define SM_BFF   6912                    // 384 floats
#define SM_P0    9216                    // act plane 0: 512 rows x 128B
#define SM_P1    (SM_P0 + 65536)         // act plane 1
#define SMEM_BYTES (SM_P1 + 65536)       // 140288

// ---------------- helpers ----------------
__device__ __forceinline__ uint32_t smem_u32(const void* p) {
    uint32_t a;
    asm("{ .reg .u64 t; cvta.to.shared.u64 t, %1; cvt.u32.u64 %0, t; }"
        : "=r"(a) : "l"(p));
    return a;
}
__device__ __forceinline__ void mma16816(float* d, const uint4& a,
                                         uint32_t b0, uint32_t b1) {
    asm volatile(
        "mma.sync.aligned.m16n8k16.row.col.f32.f16.f16.f32 "
        "{%0,%1,%2,%3}, {%4,%5,%6,%7}, {%8,%9}, {%0,%1,%2,%3};"
        : "+f"(d[0]), "+f"(d[1]), "+f"(d[2]), "+f"(d[3])
        : "r"(a.x), "r"(a.y), "r"(a.z), "r"(a.w), "r"(b0), "r"(b1));
}
__device__ __forceinline__ void ldmx4t(uint32_t& r0, uint32_t& r1,
                                       uint32_t& r2, uint32_t& r3,
                                       uint32_t addr) {
    asm volatile(
        "ldmatrix.sync.aligned.m8n8.x4.trans.shared.b16 {%0,%1,%2,%3}, [%4];"
        : "=r"(r0), "=r"(r1), "=r"(r2), "=r"(r3) : "r"(addr));
}
__device__ __forceinline__ uint16_t hfb(float v) {
    __half h = __float2half_rn(v);
    return *reinterpret_cast<uint16_t*>(&h);
}
__device__ __forceinline__ float hff(uint16_t b) {
    __half h = *reinterpret_cast<__half*>(&b);
    return __half2float(h);
}

// store v (fp16) to (row, col n) in a plane, swizzled
__device__ __forceinline__ void store1(unsigned char* plane, int row, int n, float v) {
    uint32_t off = (uint32_t)row * 128u + (((uint32_t)n * 2u) ^ (((uint32_t)row & 7u) << 4));
    *(uint16_t*)(plane + off) = hfb(v);
}

// ---------------- weight prep: fp32 -> fragment-ordered fp16 ----------------
__global__ void prep_weights(const float* __restrict__ Wf,
                             const float* __restrict__ Wh) {
    int idx = blockIdx.x * blockDim.x + threadIdx.x;
    if (idx >= PLANE_U32) return;
    int tile = idx >> 7;
    int li   = idx & 127;
    int lane = li >> 2, q = li & 3;

    const float* src; int K, mt, ks;
    if (tile < 512) { mt = tile >> 4; ks = tile & 15; K = 256; src = Wf; }
    else {
        int th = tile - 512;
        int l = th >> 10, tt = th & 1023;
        mt = tt >> 5; ks = tt & 31; K = 512;
        src = Wh + (size_t)l * 512 * 512;
    }
    int r  = lane >> 2, c2 = (lane & 3) * 2;
    int row = mt * 16 + r + (q & 1) * 8;
    int k   = ks * 16 + c2 + (q >> 1) * 8;
    float w0 = src[(size_t)row * K + k];
    float w1 = src[(size_t)row * K + k + 1];
    g_wfrag[idx] = ((uint32_t)hfb(w1) << 16) | (uint32_t)hfb(w0);
}

// ---------------- one sine layer: src plane -> dst plane ----------------
template <int KS>
__device__ __forceinline__ void run_layer(
    unsigned char* dst, uint32_t src_u32,
    const uint32_t* __restrict__ whi,
    const float* __restrict__ bias,
    int wid, int lane)
{
    float acc[2][8][4];
#pragma unroll
    for (int a = 0; a < 2; ++a)
#pragma unroll
        for (int b = 0; b < 8; ++b)
#pragma unroll
            for (int c = 0; c < 4; ++c) acc[a][b][c] = 0.0f;

    const int r  = lane >> 2;
    const int cq = lane & 3;
    const int mid  = lane >> 3;
    const int rrow = lane & 7;
    const uint32_t rswz = (uint32_t)rrow << 4;
    const uint32_t krow_off = ((uint32_t)((mid & 1) * 8 + rrow)) * 128u;
    const uint32_t nb_base  = (uint32_t)((mid >> 1) * 8) * 2u;

    const uint32_t* pA0 = whi + (size_t)((wid * 2 + 0) * KS) * 128 + lane * 4;
    const uint32_t* pA1 = whi + (size_t)((wid * 2 + 1) * KS) * 128 + lane * 4;

    // per-warp ldmatrix base addresses for the 4 n-groups (hoisted)
    uint32_t baddr[4];
#pragma unroll
    for (int j = 0; j < 4; ++j)
        baddr[j] = src_u32 + krow_off + (((uint32_t)j * 32u + nb_base) ^ rswz);

    // prologue: A and B for ks=0
    uint4 A0 = *(const uint4*)pA0;
    uint4 A1 = *(const uint4*)pA1;
    uint32_t B0[16], B1[16];
#pragma unroll
    for (int j = 0; j < 4; ++j)
        ldmx4t(B0[4 * j], B0[4 * j + 1], B0[4 * j + 2], B0[4 * j + 3],
               baddr[j]);

#pragma unroll 1
    for (int ks = 0; ks < KS; ks += 2) {
        // ---- even step (ks): prefetch A(ks+1), B(ks+1); MMA on A,B0 ----
        uint4 nA0 = *(const uint4*)(pA0 + (ks + 1) * 128);
        uint4 nA1 = *(const uint4*)(pA1 + (ks + 1) * 128);
        {
            const uint32_t kb = (uint32_t)(ks + 1) * 2048u;
#pragma unroll
            for (int j = 0; j < 4; ++j)
                ldmx4t(B1[4 * j], B1[4 * j + 1], B1[4 * j + 2], B1[4 * j + 3],
                       baddr[j] + kb);
        }
#pragma unroll
        for (int nt = 0; nt < 8; ++nt) {
            mma16816(acc[0][nt], A0, B0[nt * 2], B0[nt * 2 + 1]);
            mma16816(acc[1][nt], A1, B0[nt * 2], B0[nt * 2 + 1]);
        }

        // ---- odd step (ks+1): prefetch A(ks+2), B(ks+2); MMA on nA,B1 ----
        if (ks + 2 < KS) {
            A0 = *(const uint4*)(pA0 + (ks + 2) * 128);
            A1 = *(const uint4*)(pA1 + (ks + 2) * 128);
            const uint32_t kb = (uint32_t)(ks + 2) * 2048u;
#pragma unroll
            for (int j = 0; j < 4; ++j)
                ldmx4t(B0[4 * j], B0[4 * j + 1], B0[4 * j + 2], B0[4 * j + 3],
                       baddr[j] + kb);
        }
#pragma unroll
        for (int nt = 0; nt < 8; ++nt) {
            mma16816(acc[0][nt], nA0, B1[nt * 2], B1[nt * 2 + 1]);
            mma16816(acc[1][nt], nA1, B1[nt * 2], B1[nt * 2 + 1]);
        }
    }

    // ---- epilogue: sin -> f16x2 pack -> STS to dst ----
#pragma unroll
    for (int mtl = 0; mtl < 2; ++mtl) {
        const int row0 = wid * 32 + mtl * 16 + r;
        const int row1 = row0 + 8;
        const float ob0 = OMEGA0 * __ldg(bias + row0);
        const float ob1 = OMEGA0 * __ldg(bias + row1);
        const uint32_t sw0 = ((uint32_t)row0 & 7u) << 4;
        const uint32_t sw1 = ((uint32_t)row1 & 7u) << 4;
#pragma unroll
        for (int nt = 0; nt < 8; ++nt) {
            const int n = nt * 8 + cq * 2;
            float v00 = __sinf(fmaf(OMEGA0, acc[mtl][nt][0], ob0));
            float v01 = __sinf(fmaf(OMEGA0, acc[mtl][nt][1], ob0));
            float v10 = __sinf(fmaf(OMEGA0, acc[mtl][nt][2], ob1));
            float v11 = __sinf(fmaf(OMEGA0, acc[mtl][nt][3], ob1));
            uint32_t hp0, hp1;
            asm("cvt.rn.f16x2.f32 %0, %1, %2;"
                : "=r"(hp0) : "f"(v01), "f"(v00));
            asm("cvt.rn.f16x2.f32 %0, %1, %2;"
                : "=r"(hp1) : "f"(v11), "f"(v10));
            uint32_t off0 = (uint32_t)row0 * 128u + (((uint32_t)n * 2u) ^ sw0);
            uint32_t off1 = (uint32_t)row1 * 128u + (((uint32_t)n * 2u) ^ sw1);
            *(uint32_t*)(dst + off0) = hp0;
            *(uint32_t*)(dst + off1) = hp1;
        }
    }
    __syncthreads();   // dst visible; src free for reuse as next dst
}

// ---------------- main kernel ----------------
__global__ void __launch_bounds__(THREADS, 1)
inr_mma_kernel(const float* __restrict__ coords,
               const float* __restrict__ B_ff,
               const float* __restrict__ b_first,
               const float* __restrict__ b_hidden,
               const float* __restrict__ W_out,
               const float* __restrict__ b_out,
               float* __restrict__ out, int L)
{
    extern __shared__ unsigned char sm[];
    float* wout = (float*)(sm + SM_WOUT);
    float* cs   = (float*)(sm + SM_CS);
    float* bff  = (float*)(sm + SM_BFF);
    unsigned char* p0 = sm + SM_P0;
    unsigned char* p1 = sm + SM_P1;
    const uint32_t p0u = smem_u32(p0);
    const uint32_t p1u = smem_u32(p1);

    const int tid  = threadIdx.x;
    const int wid  = tid >> 5;
    const int lane = tid & 31;
    const int pt0  = blockIdx.x * 64;

    if (tid < 192) {
        int g = pt0 * 3 + tid;
        cs[tid] = (g < L * 3) ? coords[g] : 0.0f;
    }
    for (int i = tid; i < 384; i += THREADS) bff[i] = B_ff[i];
    __syncthreads();

    // Fourier features -> plane 0. sin(2*pi*t) == sin(2*pi*(t - rint(t))).
    for (int e = tid; e < 8192; e += THREADS) {
        int j = e >> 6, m = e & 63;
        float t = cs[m * 3 + 0] * bff[j] +
                  cs[m * 3 + 1] * bff[128 + j] +
                  cs[m * 3 + 2] * bff[256 + j];
        float f = t - rintf(t);
        float ang = TWO_PI_F * f;
        store1(p0, j, m, __sinf(ang));
        store1(p0, 128 + j, m, __cosf(ang));
    }
    __syncthreads();

    // layer 0: K=256, P0 -> P1
    run_layer<16>(p1, p0u, g_wfrag, b_first, wid, lane);
    // hidden layers: K=512, alternate planes (l even: P1->P0, odd: P0->P1)
#pragma unroll 1
    for (int l = 0; l < 5; ++l) {
        const size_t base = (size_t)(512 + l * 1024) * 128;
        unsigned char* dst = (l & 1) ? p1 : p0;
        uint32_t src = (l & 1) ? p0u : p1u;
        run_layer<32>(dst, src, g_wfrag + base,
                      b_hidden + l * 512, wid, lane);
    }
    // after 5 hidden layers (l=0..4): final activations in P0

    // ---- output linear 512 -> 3: all 512 threads (8 k-slices per point) ----
    for (int f = tid; f < 1536; f += THREADS) wout[f] = W_out[f];
    __syncthreads();
    {
        const int p = tid >> 3;        // point 0..63
        const int s = tid & 7;         // k-slice 0..7
        float a0 = 0.0f, a1 = 0.0f, a2 = 0.0f;
#pragma unroll 4
        for (int kk = 0; kk < 64; ++kk) {
            const int k = s * 64 + kk;
            uint32_t off = (uint32_t)k * 128u +
                           (((uint32_t)p * 2u) ^ (((uint32_t)k & 7u) << 4));
            float hv = hff(*(uint16_t*)(p0 + off));
            a0 = fmaf(hv, wout[k], a0);
            a1 = fmaf(hv, wout[512 + k], a1);
            a2 = fmaf(hv, wout[1024 + k], a2);
        }
#pragma unroll
        for (int d = 4; d >= 1; d >>= 1) {
            a0 += __shfl_down_sync(0xFFFFFFFFu, a0, d);
            a1 += __shfl_down_sync(0xFFFFFFFFu, a1, d);
            a2 += __shfl_down_sync(0xFFFFFFFFu, a2, d);
        }
        if (s == 0) {
            int gp = pt0 + p;
            if (gp < L) {
                out[gp * 3 + 0] = a0 + __ldg(b_out + 0);
                out[gp * 3 + 1] = a1 + __ldg(b_out + 1);
                out[gp * 3 + 2] = a2 + __ldg(b_out + 2);
            }
        }
    }
}

// ---------------- launcher ----------------
extern "C" void kernel_launch(void* const* d_in, const int* in_sizes, int n_in,
                              void* d_out, int out_size) {
    const float* coords   = (const float*)d_in[0];
    const float* B_ff     = (const float*)d_in[1];
    const float* W_first  = (const float*)d_in[2];
    const float* b_first  = (const float*)d_in[3];
    const float* W_hidden = (const float*)d_in[4];
    const float* b_hidden = (const float*)d_in[5];
    const float* W_out    = (const float*)d_in[6];
    const float* b_out    = (const float*)d_in[7];
    float* out = (float*)d_out;

    int L = in_sizes[0] / 3;
    int tiles = (L + 63) / 64;

    prep_weights<<<(PLANE_U32 + 255) / 256, 256>>>(W_first, W_hidden);

    cudaFuncSetAttribute(inr_mma_kernel,
                         cudaFuncAttributeMaxDynamicSharedMemorySize,
                         SMEM_BYTES);
    inr_mma_kernel<<<tiles, THREADS, SMEM_BYTES>>>(
        coords, B_ff, b_first, b_hidden, W_out, b_out, out, L);
}

// round 13
// speedup vs baseline: 1.8138x; 1.0742x over previous
#include <cuda_runtime.h>
#include <cuda_fp16.h>
#include <math.h>
#include <stdint.h>

// ===========================================================================
// Fused INR via warp-level mma.sync, fp16 weights/acts, fp32 accum.
// R12: 256 threads / 8 warps, warp = 64 neurons x 64 points (4mt x 8nt).
//      Same MMA count as R11; B-tile LDSM duplication halved (16x -> 8x)
//      => SM L1 wavefronts per k-step 384 -> 256.
// ===========================================================================

#define OMEGA0    30.0f
#define TWO_PI_F  6.283185307179586f
#define THREADS   256

#define NTILES    (512 + 5 * 1024)      // 5632 (mt,ks) tiles total
#define PLANE_U32 (NTILES * 128)        // u32 per plane (tile=128 u32)

__device__ __align__(16) uint32_t g_wfrag[PLANE_U32];   // fp16 weight fragments

// ---- SMEM layout (bytes) ----
#define SM_WOUT  0                       // 1536 floats
#define SM_CS    6144                    // 192 floats
#define SM_BFF   6912                    // 384 floats
#define SM_P0    9216                    // act plane 0: 512 rows x 128B
#define SM_P1    (SM_P0 + 65536)         // act plane 1
#define SMEM_BYTES (SM_P1 + 65536)       // 140288

// ---------------- helpers ----------------
__device__ __forceinline__ uint32_t smem_u32(const void* p) {
    uint32_t a;
    asm("{ .reg .u64 t; cvta.to.shared.u64 t, %1; cvt.u32.u64 %0, t; }"
        : "=r"(a) : "l"(p));
    return a;
}
__device__ __forceinline__ void mma16816(float* d, const uint4& a,
                                         uint32_t b0, uint32_t b1) {
    asm volatile(
        "mma.sync.aligned.m16n8k16.row.col.f32.f16.f16.f32 "
        "{%0,%1,%2,%3}, {%4,%5,%6,%7}, {%8,%9}, {%0,%1,%2,%3};"
        : "+f"(d[0]), "+f"(d[1]), "+f"(d[2]), "+f"(d[3])
        : "r"(a.x), "r"(a.y), "r"(a.z), "r"(a.w), "r"(b0), "r"(b1));
}
__device__ __forceinline__ void ldmx4t(uint32_t& r0, uint32_t& r1,
                                       uint32_t& r2, uint32_t& r3,
                                       uint32_t addr) {
    asm volatile(
        "ldmatrix.sync.aligned.m8n8.x4.trans.shared.b16 {%0,%1,%2,%3}, [%4];"
        : "=r"(r0), "=r"(r1), "=r"(r2), "=r"(r3) : "r"(addr));
}
__device__ __forceinline__ uint16_t hfb(float v) {
    __half h = __float2half_rn(v);
    return *reinterpret_cast<uint16_t*>(&h);
}
__device__ __forceinline__ float hff(uint16_t b) {
    __half h = *reinterpret_cast<__half*>(&b);
    return __half2float(h);
}

// store v (fp16) to (row, col n) in a plane, swizzled
__device__ __forceinline__ void store1(unsigned char* plane, int row, int n, float v) {
    uint32_t off = (uint32_t)row * 128u + (((uint32_t)n * 2u) ^ (((uint32_t)row & 7u) << 4));
    *(uint16_t*)(plane + off) = hfb(v);
}

// ---------------- weight prep: fp32 -> fragment-ordered fp16 ----------------
__global__ void prep_weights(const float* __restrict__ Wf,
                             const float* __restrict__ Wh) {
    int idx = blockIdx.x * blockDim.x + threadIdx.x;
    if (idx >= PLANE_U32) return;
    int tile = idx >> 7;
    int li   = idx & 127;
    int lane = li >> 2, q = li & 3;

    const float* src; int K, mt, ks;
    if (tile < 512) { mt = tile >> 4; ks = tile & 15; K = 256; src = Wf; }
    else {
        int th = tile - 512;
        int l = th >> 10, tt = th & 1023;
        mt = tt >> 5; ks = tt & 31; K = 512;
        src = Wh + (size_t)l * 512 * 512;
    }
    int r  = lane >> 2, c2 = (lane & 3) * 2;
    int row = mt * 16 + r + (q & 1) * 8;
    int k   = ks * 16 + c2 + (q >> 1) * 8;
    float w0 = src[(size_t)row * K + k];
    float w1 = src[(size_t)row * K + k + 1];
    g_wfrag[idx] = ((uint32_t)hfb(w1) << 16) | (uint32_t)hfb(w0);
}

// ---------------- one sine layer: src plane -> dst plane ----------------
template <int KS>
__device__ __forceinline__ void run_layer(
    unsigned char* dst, uint32_t src_u32,
    const uint32_t* __restrict__ whi,
    const float* __restrict__ bias,
    int wid, int lane)
{
    float acc[4][8][4];     // [m-tile][n-tile][frag]
#pragma unroll
    for (int a = 0; a < 4; ++a)
#pragma unroll
        for (int b = 0; b < 8; ++b)
#pragma unroll
            for (int c = 0; c < 4; ++c) acc[a][b][c] = 0.0f;

    const int r  = lane >> 2;
    const int cq = lane & 3;
    const int mid  = lane >> 3;
    const int rrow = lane & 7;
    const uint32_t rswz = (uint32_t)rrow << 4;
    const uint32_t krow_off = ((uint32_t)((mid & 1) * 8 + rrow)) * 128u;
    const uint32_t nb_base  = (uint32_t)((mid >> 1) * 8) * 2u;

    const uint32_t* pA[4];
#pragma unroll
    for (int mt = 0; mt < 4; ++mt)
        pA[mt] = whi + (size_t)((wid * 4 + mt) * KS) * 128 + lane * 4;

    uint32_t baddr[4];
#pragma unroll
    for (int j = 0; j < 4; ++j)
        baddr[j] = src_u32 + krow_off + (((uint32_t)j * 32u + nb_base) ^ rswz);

    // prologue: A and B for ks=0
    uint4 A[4], nA[4];
#pragma unroll
    for (int mt = 0; mt < 4; ++mt) A[mt] = *(const uint4*)pA[mt];
    uint32_t B0[16], B1[16];
#pragma unroll
    for (int j = 0; j < 4; ++j)
        ldmx4t(B0[4 * j], B0[4 * j + 1], B0[4 * j + 2], B0[4 * j + 3],
               baddr[j]);

#pragma unroll 1
    for (int ks = 0; ks < KS; ks += 2) {
        // ---- even step: prefetch A(ks+1), B(ks+1); MMA on A,B0 ----
#pragma unroll
        for (int mt = 0; mt < 4; ++mt)
            nA[mt] = *(const uint4*)(pA[mt] + (ks + 1) * 128);
        {
            const uint32_t kb = (uint32_t)(ks + 1) * 2048u;
#pragma unroll
            for (int j = 0; j < 4; ++j)
                ldmx4t(B1[4 * j], B1[4 * j + 1], B1[4 * j + 2], B1[4 * j + 3],
                       baddr[j] + kb);
        }
#pragma unroll
        for (int nt = 0; nt < 8; ++nt)
#pragma unroll
            for (int mt = 0; mt < 4; ++mt)
                mma16816(acc[mt][nt], A[mt], B0[nt * 2], B0[nt * 2 + 1]);

        // ---- odd step: prefetch A(ks+2), B(ks+2); MMA on nA,B1 ----
        if (ks + 2 < KS) {
#pragma unroll
            for (int mt = 0; mt < 4; ++mt)
                A[mt] = *(const uint4*)(pA[mt] + (ks + 2) * 128);
            const uint32_t kb = (uint32_t)(ks + 2) * 2048u;
#pragma unroll
            for (int j = 0; j < 4; ++j)
                ldmx4t(B0[4 * j], B0[4 * j + 1], B0[4 * j + 2], B0[4 * j + 3],
                       baddr[j] + kb);
        }
#pragma unroll
        for (int nt = 0; nt < 8; ++nt)
#pragma unroll
            for (int mt = 0; mt < 4; ++mt)
                mma16816(acc[mt][nt], nA[mt], B1[nt * 2], B1[nt * 2 + 1]);
    }

    // ---- epilogue: sin -> f16x2 pack -> STS to dst ----
#pragma unroll
    for (int mtl = 0; mtl < 4; ++mtl) {
        const int row0 = wid * 64 + mtl * 16 + r;
        const int row1 = row0 + 8;
        const float ob0 = OMEGA0 * __ldg(bias + row0);
        const float ob1 = OMEGA0 * __ldg(bias + row1);
        const uint32_t sw0 = ((uint32_t)row0 & 7u) << 4;
        const uint32_t sw1 = ((uint32_t)row1 & 7u) << 4;
#pragma unroll
        for (int nt = 0; nt < 8; ++nt) {
            const int n = nt * 8 + cq * 2;
            float v00 = __sinf(fmaf(OMEGA0, acc[mtl][nt][0], ob0));
            float v01 = __sinf(fmaf(OMEGA0, acc[mtl][nt][1], ob0));
            float v10 = __sinf(fmaf(OMEGA0, acc[mtl][nt][2], ob1));
            float v11 = __sinf(fmaf(OMEGA0, acc[mtl][nt][3], ob1));
            uint32_t hp0, hp1;
            asm("cvt.rn.f16x2.f32 %0, %1, %2;"
                : "=r"(hp0) : "f"(v01), "f"(v00));
            asm("cvt.rn.f16x2.f32 %0, %1, %2;"
                : "=r"(hp1) : "f"(v11), "f"(v10));
            uint32_t off0 = (uint32_t)row0 * 128u + (((uint32_t)n * 2u) ^ sw0);
            uint32_t off1 = (uint32_t)row1 * 128u + (((uint32_t)n * 2u) ^ sw1);
            *(uint32_t*)(dst + off0) = hp0;
            *(uint32_t*)(dst + off1) = hp1;
        }
    }
    __syncthreads();   // dst visible; src free for reuse as next dst
}

// ---------------- main kernel ----------------
__global__ void __launch_bounds__(THREADS, 1)
inr_mma_kernel(const float* __restrict__ coords,
               const float* __restrict__ B_ff,
               const float* __restrict__ b_first,
               const float* __restrict__ b_hidden,
               const float* __restrict__ W_out,
               const float* __restrict__ b_out,
               float* __restrict__ out, int L)
{
    extern __shared__ unsigned char sm[];
    float* wout = (float*)(sm + SM_WOUT);
    float* cs   = (float*)(sm + SM_CS);
    float* bff  = (float*)(sm + SM_BFF);
    unsigned char* p0 = sm + SM_P0;
    unsigned char* p1 = sm + SM_P1;
    const uint32_t p0u = smem_u32(p0);
    const uint32_t p1u = smem_u32(p1);

    const int tid  = threadIdx.x;
    const int wid  = tid >> 5;
    const int lane = tid & 31;
    const int pt0  = blockIdx.x * 64;

    if (tid < 192) {
        int g = pt0 * 3 + tid;
        cs[tid] = (g < L * 3) ? coords[g] : 0.0f;
    }
    for (int i = tid; i < 384; i += THREADS) bff[i] = B_ff[i];
    __syncthreads();

    // Fourier features -> plane 0. sin(2*pi*t) == sin(2*pi*(t - rint(t))).
    for (int e = tid; e < 8192; e += THREADS) {
        int j = e >> 6, m = e & 63;
        float t = cs[m * 3 + 0] * bff[j] +
                  cs[m * 3 + 1] * bff[128 + j] +
                  cs[m * 3 + 2] * bff[256 + j];
        float f = t - rintf(t);
        float ang = TWO_PI_F * f;
        store1(p0, j, m, __sinf(ang));
        store1(p0, 128 + j, m, __cosf(ang));
    }
    __syncthreads();

    // layer 0: K=256, P0 -> P1
    run_layer<16>(p1, p0u, g_wfrag, b_first, wid, lane);
    // hidden layers: K=512, alternate planes (l even: P1->P0, odd: P0->P1)
#pragma unroll 1
    for (int l = 0; l < 5; ++l) {
        const size_t base = (size_t)(512 + l * 1024) * 128;
        unsigned char* dst = (l & 1) ? p1 : p0;
        uint32_t src = (l & 1) ? p0u : p1u;
        run_layer<32>(dst, src, g_wfrag + base,
                      b_hidden + l * 512, wid, lane);
    }
    // after 5 hidden layers (l=0..4): final activations in P0

    // ---- output linear 512 -> 3: 256 threads, 4 k-slices per point ----
    for (int f = tid; f < 1536; f += THREADS) wout[f] = W_out[f];
    __syncthreads();
    {
        const int p = tid >> 2;        // point 0..63
        const int s = tid & 3;         // k-slice 0..3
        float a0 = 0.0f, a1 = 0.0f, a2 = 0.0f;
#pragma unroll 4
        for (int kk = 0; kk < 128; ++kk) {
            const int k = s * 128 + kk;
            uint32_t off = (uint32_t)k * 128u +
                           (((uint32_t)p * 2u) ^ (((uint32_t)k & 7u) << 4));
            float hv = hff(*(uint16_t*)(p0 + off));
            a0 = fmaf(hv, wout[k], a0);
            a1 = fmaf(hv, wout[512 + k], a1);
            a2 = fmaf(hv, wout[1024 + k], a2);
        }
#pragma unroll
        for (int d = 2; d >= 1; d >>= 1) {
            a0 += __shfl_down_sync(0xFFFFFFFFu, a0, d, 4);
            a1 += __shfl_down_sync(0xFFFFFFFFu, a1, d, 4);
            a2 += __shfl_down_sync(0xFFFFFFFFu, a2, d, 4);
        }
        if (s == 0) {
            int gp = pt0 + p;
            if (gp < L) {
                out[gp * 3 + 0] = a0 + __ldg(b_out + 0);
                out[gp * 3 + 1] = a1 + __ldg(b_out + 1);
                out[gp * 3 + 2] = a2 + __ldg(b_out + 2);
            }
        }
    }
}

// ---------------- launcher ----------------
extern "C" void kernel_launch(void* const* d_in, const int* in_sizes, int n_in,
                              void* d_out, int out_size) {
    const float* coords   = (const float*)d_in[0];
    const float* B_ff     = (const float*)d_in[1];
    const float* W_first  = (const float*)d_in[2];
    const float* b_first  = (const float*)d_in[3];
    const float* W_hidden = (const float*)d_in[4];
    const float* b_hidden = (const float*)d_in[5];
    const float* W_out    = (const float*)d_in[6];
    const float* b_out    = (const float*)d_in[7];
    float* out = (float*)d_out;

    int L = in_sizes[0] / 3;
    int tiles = (L + 63) / 64;

    prep_weights<<<(PLANE_U32 + 255) / 256, 256>>>(W_first, W_hidden);

    cudaFuncSetAttribute(inr_mma_kernel,
                         cudaFuncAttributeMaxDynamicSharedMemorySize,
                         SMEM_BYTES);
    inr_mma_kernel<<<tiles, THREADS, SMEM_BYTES>>>(
        coords, B_ff, b_first, b_hidden, W_out, b_out, out, L);
}